// round 16
// baseline (speedup 1.0000x reference)
#include <cuda_runtime.h>
#include <cuda_fp16.h>
#include <cstdint>
#include <cstddef>

typedef unsigned long long u64;
typedef unsigned int u32;

#define NROWS  65536
#define LATENT 256
#define NNODES 256
#define TM     128
#define NT     512
#define GRID   (NROWS / TM)   // 512
#define EPSF   1.1920929e-7f
#define MARGIN 0.02f
#define CAP    2048

// ---- smem layout (byte offsets from 1KB-aligned base) ----
#define SA_OFF(s) ((s) * 49152)            // A stage: 128 rows x 128B fp16 (16KB)
#define SB_OFF(s) ((s) * 49152 + 16384)    // B stage: 256 rows x 128B fp16 (32KB)
#define T_LIST  0                          // overlays stage mem (dead post-GEMM)
#define T_E2RAW 98304
#define T_E2D   99328
#define T_E2P   100352
#define T_Z2P   102400
#define T_Z2RAW 104448
#define T_Z2PP  104960
#define T_RQM   105472
#define T_RQS   107520
#define T_QTHR  109568
#define T_RQSI  110080
#define T_KEY   110592
#define T_BMU   111616
#define T_CNT   112128
#define T_TAB   112144                     // 768 * 8 = 6144
#define SMEM_BYTES (118288 + 1024)

__device__ __forceinline__ u32 smaddr(const void* p) { return (u32)__cvta_generic_to_shared(p); }
__device__ __forceinline__ u32 toff(int row, int kbyte) {
    u32 o = (u32)(row * 128 + kbyte);
    return o ^ ((o >> 3) & 0x70);          // SW128 (XORs bits 4-6; 8/16B-aligned stores stay aligned)
}
__device__ __forceinline__ void ldsm4(u32* r, u32 addr) {
    asm volatile("ldmatrix.sync.aligned.m8n8.x4.shared.b16 {%0,%1,%2,%3}, [%4];"
                 : "=r"(r[0]), "=r"(r[1]), "=r"(r[2]), "=r"(r[3]) : "r"(addr));
}
__device__ __forceinline__ void mma16816(float* d, const u32* a, u32 b0, u32 b1) {
    asm volatile("mma.sync.aligned.m16n8k16.row.col.f32.f16.f16.f32 "
                 "{%0,%1,%2,%3}, {%4,%5,%6,%7}, {%8,%9}, {%0,%1,%2,%3};"
                 : "+f"(d[0]), "+f"(d[1]), "+f"(d[2]), "+f"(d[3])
                 : "r"(a[0]), "r"(a[1]), "r"(a[2]), "r"(a[3]), "r"(b0), "r"(b1));
}
__device__ __forceinline__ u64 packf2(float lo, float hi) {
    u64 d; asm("mov.b64 %0, {%1, %2};" : "=l"(d) : "f"(lo), "f"(hi)); return d;
}
__device__ __forceinline__ void unpackf2(float& lo, float& hi, u64 v) {
    asm("mov.b64 {%0, %1}, %2;" : "=f"(lo), "=f"(hi) : "l"(v));
}
__device__ __forceinline__ u64 add2(u64 a, u64 b) {
    u64 d; asm("add.rn.f32x2 %0, %1, %2;" : "=l"(d) : "l"(a), "l"(b)); return d;
}
__device__ __forceinline__ u64 mul2(u64 a, u64 b) {
    u64 d; asm("mul.rn.f32x2 %0, %1, %2;" : "=l"(d) : "l"(a), "l"(b)); return d;
}
__device__ __forceinline__ u64 fma2(u64 a, u64 b, u64 c) {
    u64 d; asm("fma.rn.f32x2 %0, %1, %2, %3;" : "=l"(d) : "l"(a), "l"(b), "l"(c)); return d;
}
__device__ __forceinline__ u64 cvt4fp16(float4 v) {
    __half2 p0 = __floats2half2_rn(v.x, v.y);
    __half2 p1 = __floats2half2_rn(v.z, v.w);
    u32 a = *(u32*)&p0, b = *(u32*)&p1;
    return ((u64)b << 32) | (u64)a;
}

__global__ void __launch_bounds__(NT, 1)
som_main(const float* __restrict__ Z, const float* __restrict__ E,
         const int* __restrict__ Alpha, float* __restrict__ out)
{
    extern __shared__ char smraw[];
    char* SB = (char*)(((uintptr_t)smraw + 1023) & ~(uintptr_t)1023);
    float* e2raw = (float*)(SB + T_E2RAW);
    float* e2d   = (float*)(SB + T_E2D);
    float* e2p   = (float*)(SB + T_E2P);
    float* z2p   = (float*)(SB + T_Z2P);
    float* z2raw = (float*)(SB + T_Z2RAW);
    float* z2pp  = (float*)(SB + T_Z2PP);
    float* rqm   = (float*)(SB + T_RQM);
    float* rqsum = (float*)(SB + T_RQS);
    float* qthr  = (float*)(SB + T_QTHR);
    float* rqs   = (float*)(SB + T_RQSI);
    u64*   keyA  = (u64*)(SB + T_KEY);
    int*   bmuS  = (int*)(SB + T_BMU);
    int*   cnt   = (int*)(SB + T_CNT);
    u64*   tab   = (u64*)(SB + T_TAB);
    u32*   list  = (u32*)(SB + T_LIST);

    const int t = threadIdx.x, wid = t >> 5, lane = t & 31;
    const int g = lane >> 2, qd = lane & 3;
    const int R0 = blockIdx.x * TM;
    const int wr = (wid >> 2) * 32, wc = (wid & 3) * 64;
    const int arow = t >> 2, akp = t & 3;   // A build: 4 threads/row, 16 floats each

    // alpha (robust)
    int ai = Alpha[0];
    float aa = (ai > 0 && ai < 1000000) ? (float)ai : __int_as_float(ai);
    const float inva = 1.0f / aa;
    const float coef = -(aa + 1.0f) * 0.5f;
    const bool fast = (aa == 10.0f);
    const u64 cm2 = packf2(-2.f * inva, -2.f * inva);

    if (t < TM) keyA[t] = ~0ull;
    if (t == 0) *cnt = 0;

    float z2acc = 0.f;

    // ---- prologue: issue A chunk-0 DRAM loads first ----
    float4 a0[4];
    {
        const float4* zsrc = (const float4*)(Z + (size_t)(R0 + arow) * LATENT + akp * 16);
        a0[0] = zsrc[0]; a0[1] = zsrc[1]; a0[2] = zsrc[2]; a0[3] = zsrc[3];
    }
    // e2 partials: 2 threads/node, HALF-ROW (128 floats) each — full coverage
    {
        int node = t >> 1, part = t & 1;
        const float4* er = (const float4*)(E + (size_t)node * LATENT + part * 128);
        float s2 = 0.f;
        #pragma unroll 8
        for (int i = 0; i < 32; i++) { float4 v = er[i]; s2 += v.x*v.x + v.y*v.y + v.z*v.z + v.w*v.w; }
        e2p[t] = s2;
    }
    // B chunk 0 build (L2-resident E), two 4-wide batches
    #pragma unroll
    for (int h = 0; h < 2; h++) {
        float4 w[4];
        #pragma unroll
        for (int i = 0; i < 4; i++) {
            int v = t + NT * (h * 4 + i);
            int node = v >> 4, q16 = v & 15;
            w[i] = *(const float4*)(E + (size_t)node * LATENT + q16 * 4);
        }
        #pragma unroll
        for (int i = 0; i < 4; i++) {
            int v = t + NT * (h * 4 + i);
            int node = v >> 4, q16 = v & 15;
            *(u64*)(SB + SB_OFF(0) + toff(node, q16 * 8)) = cvt4fp16(w[i]);
        }
    }
    // A chunk 0 convert + store
    {
        #pragma unroll
        for (int i = 0; i < 4; i++) {
            float4 w = a0[i];
            z2acc = fmaf(w.x,w.x,fmaf(w.y,w.y,fmaf(w.z,w.z,fmaf(w.w,w.w,z2acc))));
        }
        ulonglong2 pk0, pk1;
        pk0.x = cvt4fp16(a0[0]); pk0.y = cvt4fp16(a0[1]);
        pk1.x = cvt4fp16(a0[2]); pk1.y = cvt4fp16(a0[3]);
        *(ulonglong2*)(SB + SA_OFF(0) + toff(arow, akp * 32))      = pk0;
        *(ulonglong2*)(SB + SA_OFF(0) + toff(arow, akp * 32 + 16)) = pk1;
    }

    // ---- GEMM: 4 chunks, A+B both double-buffered, built in-loop ----
    float acc[2][8][4];
    #pragma unroll
    for (int mt = 0; mt < 2; mt++)
        #pragma unroll
        for (int j = 0; j < 8; j++)
            #pragma unroll
            for (int c4 = 0; c4 < 4; c4++) acc[mt][j][c4] = 0.f;

    const int la = lane & 15, kh = lane >> 4;
    for (int c = 0; c < 4; c++) {
        const int s = c & 1;
        __syncthreads();   // stage s fully built; prior MMAs done with stage s^1

        if (c < 3) {       // build A+B chunk c+1 into stage s^1 (absorbed by MMA slack)
            // A
            const float4* zsrc = (const float4*)(Z + (size_t)(R0 + arow) * LATENT + (c + 1) * 64 + akp * 16);
            float4 w0 = zsrc[0], w1 = zsrc[1], w2 = zsrc[2], w3 = zsrc[3];
            z2acc = fmaf(w0.x,w0.x,fmaf(w0.y,w0.y,fmaf(w0.z,w0.z,fmaf(w0.w,w0.w,z2acc))));
            z2acc = fmaf(w1.x,w1.x,fmaf(w1.y,w1.y,fmaf(w1.z,w1.z,fmaf(w1.w,w1.w,z2acc))));
            z2acc = fmaf(w2.x,w2.x,fmaf(w2.y,w2.y,fmaf(w2.z,w2.z,fmaf(w2.w,w2.w,z2acc))));
            z2acc = fmaf(w3.x,w3.x,fmaf(w3.y,w3.y,fmaf(w3.z,w3.z,fmaf(w3.w,w3.w,z2acc))));
            ulonglong2 pk0, pk1;
            pk0.x = cvt4fp16(w0); pk0.y = cvt4fp16(w1);
            pk1.x = cvt4fp16(w2); pk1.y = cvt4fp16(w3);
            *(ulonglong2*)(SB + SA_OFF(1 - s) + toff(arow, akp * 32))      = pk0;
            *(ulonglong2*)(SB + SA_OFF(1 - s) + toff(arow, akp * 32 + 16)) = pk1;
            // B (L2-resident)
            #pragma unroll
            for (int h = 0; h < 2; h++) {
                float4 w[4];
                #pragma unroll
                for (int i = 0; i < 4; i++) {
                    int v = t + NT * (h * 4 + i);
                    int node = v >> 4, q16 = v & 15;
                    w[i] = *(const float4*)(E + (size_t)node * LATENT + (c + 1) * 64 + q16 * 4);
                }
                #pragma unroll
                for (int i = 0; i < 4; i++) {
                    int v = t + NT * (h * 4 + i);
                    int node = v >> 4, q16 = v & 15;
                    *(u64*)(SB + SB_OFF(1 - s) + toff(node, q16 * 8)) = cvt4fp16(w[i]);
                }
            }
        }

        const u32 sAa = smaddr(SB + SA_OFF(s));
        const u32 sBa = smaddr(SB + SB_OFF(s));
        #pragma unroll
        for (int ks = 0; ks < 4; ks++) {
            const int kb = ks * 32 + kh * 16;
            u32 af[2][4];
            ldsm4(af[0], sAa + toff(wr + la, kb));
            ldsm4(af[1], sAa + toff(wr + 16 + la, kb));
            u32 bf[4][4];
            #pragma unroll
            for (int p = 0; p < 4; p++)
                ldsm4(bf[p], sBa + toff(wc + p * 16 + la, kb));
            #pragma unroll
            for (int mt = 0; mt < 2; mt++)
                #pragma unroll
                for (int j = 0; j < 8; j++)
                    mma16816(acc[mt][j], af[mt], bf[j >> 1][j & 1], bf[j >> 1][(j & 1) + 2]);
        }
    }

    // ---- z2 + e2 finalize ----
    z2p[arow * 4 + akp] = z2acc;
    __syncthreads();
    if (t < NNODES) {
        float e = e2p[2 * t] + e2p[2 * t + 1];
        e2raw[t] = e;
        e2d[t]   = e * inva;
    }
    if (t < TM) {
        float z = z2p[4*t] + z2p[4*t+1] + z2p[4*t+2] + z2p[4*t+3];
        z2raw[t] = z;
        z2pp[t]  = fmaf(z, inva, 1.0f);
    }
    __syncthreads();

    // ---- q eval (rsqrt(p^11) fast path), per-row qmax + qsum ----
    u64 ed2[8];
    #pragma unroll
    for (int j = 0; j < 8; j++) ed2[j] = *(const u64*)(e2d + wc + j * 8 + 2 * qd);
    float qmaxr[4], qsumr[4];
    #pragma unroll
    for (int mt = 0; mt < 2; mt++) {
        #pragma unroll
        for (int hf = 0; hf < 2; hf++) {
            const int row = wr + mt * 16 + hf * 8 + g;
            const u64 zp = packf2(z2pp[row], z2pp[row]);
            u64 qs2 = 0ull;
            float qmax = 0.f;
            #pragma unroll
            for (int j = 0; j < 8; j++) {
                u64 a2 = packf2(acc[mt][j][2*hf], acc[mt][j][2*hf+1]);
                u64 p  = fma2(a2, cm2, add2(zp, ed2[j]));   // p = 1 + d/alpha
                float q0, q1;
                if (fast) {
                    u64 x2 = mul2(p, p);
                    u64 x4 = mul2(x2, x2);
                    u64 x8 = mul2(x4, x4);
                    u64 x11 = mul2(mul2(x8, x2), p);
                    float lo, hi; unpackf2(lo, hi, x11);
                    q0 = rsqrtf(lo); q1 = rsqrtf(hi);
                } else {
                    float lo, hi; unpackf2(lo, hi, p);
                    q0 = exp2f(coef * __log2f(lo));
                    q1 = exp2f(coef * __log2f(hi));
                }
                qs2 = add2(qs2, packf2(q0, q1));
                qmax = fmaxf(qmax, fmaxf(q0, q1));
                acc[mt][j][2*hf] = q0;
                acc[mt][j][2*hf+1] = q1;
            }
            float slo, shi; unpackf2(slo, shi, qs2);
            qmaxr[mt*2+hf] = qmax;
            qsumr[mt*2+hf] = slo + shi;
        }
    }
    #pragma unroll
    for (int i = 0; i < 4; i++) {
        qmaxr[i] = fmaxf(qmaxr[i], __shfl_xor_sync(0xffffffffu, qmaxr[i], 1));
        qmaxr[i] = fmaxf(qmaxr[i], __shfl_xor_sync(0xffffffffu, qmaxr[i], 2));
        qsumr[i] += __shfl_xor_sync(0xffffffffu, qsumr[i], 1);
        qsumr[i] += __shfl_xor_sync(0xffffffffu, qsumr[i], 2);
    }
    if (qd == 0) {
        #pragma unroll
        for (int i = 0; i < 4; i++) {
            const int row = wr + (i >> 1) * 16 + (i & 1) * 8 + g;
            rqm[row * 4 + (wid & 3)]   = qmaxr[i];
            rqsum[row * 4 + (wid & 3)] = qsumr[i];
        }
    }
    __syncthreads();
    if (t < TM) {
        float qm = 0.f, s = 0.f;
        #pragma unroll
        for (int k = 0; k < 4; k++) { qm = fmaxf(qm, rqm[t*4+k]); s += rqsum[t*4+k]; }
        rqs[t] = 1.0f / s;
        float pmin = exp2f(__log2f(qm) / coef);
        float y = pmin + MARGIN * inva;
        float qt;
        if (fast) {
            float y2 = y*y, y4 = y2*y2, y8 = y4*y4;
            qt = rsqrtf(y8 * y2 * y);
        } else {
            qt = exp2f(coef * __log2f(y));
        }
        qthr[t] = qt;
    }
    __syncthreads();

    const size_t NBOFF  = (size_t)NROWS * 256;
    const size_t QOFF   = (size_t)NROWS * 1536;
    const size_t BMUOFF = (size_t)NROWS * 1792;

    // ---- q stores first (early DRAM burst) ----
    #pragma unroll
    for (int mt = 0; mt < 2; mt++)
        #pragma unroll
        for (int hf = 0; hf < 2; hf++) {
            const int row = wr + mt * 16 + hf * 8 + g;
            const float rq = rqs[row];
            #pragma unroll
            for (int j = 0; j < 8; j++) {
                float2 qv;
                qv.x = fmaf(acc[mt][j][2*hf],   rq, EPSF);
                qv.y = fmaf(acc[mt][j][2*hf+1], rq, EPSF);
                *(float2*)(out + QOFF + (size_t)(R0 + row) * NNODES + wc + j * 8 + 2 * qd) = qv;
            }
        }

    // ---- candidate collection (list overlays dead stage mem) ----
    #pragma unroll
    for (int mt = 0; mt < 2; mt++)
        #pragma unroll
        for (int hf = 0; hf < 2; hf++) {
            const int row = wr + mt * 16 + hf * 8 + g;
            const float th = qthr[row];
            #pragma unroll
            for (int j = 0; j < 8; j++)
                #pragma unroll
                for (int u2 = 0; u2 < 2; u2++) {
                    if (acc[mt][j][2*hf+u2] >= th) {
                        int idx = atomicAdd(cnt, 1);
                        if (idx < CAP)
                            list[idx] = ((u32)row << 8) | (u32)(wc + j * 8 + 2 * qd + u2);
                    }
                }
        }
    __syncthreads();

    // ---- exact fp32 refinement: one warp per candidate ----
    {
        const int n = min(*cnt, CAP);
        for (int e = wid; e < n; e += 16) {
            u32 ent = list[e];
            int row = ent >> 8, node = ent & 255;
            const float4* zr = (const float4*)(Z + (size_t)(R0 + row) * LATENT);
            const float4* er = (const float4*)(E + (size_t)node * LATENT);
            float4 za = zr[lane*2], zb = zr[lane*2+1];
            float4 ea = er[lane*2], eb = er[lane*2+1];
            float d = za.x*ea.x + za.y*ea.y + za.z*ea.z + za.w*ea.w
                    + zb.x*eb.x + zb.y*eb.y + zb.z*eb.z + zb.w*eb.w;
            #pragma unroll
            for (int o = 16; o > 0; o >>= 1) d += __shfl_down_sync(0xffffffffu, d, o);
            if (lane == 0) {
                float dex = fmaxf(z2raw[row] + e2raw[node] - 2.f * d, 0.f);
                u64 key = ((u64)__float_as_uint(dex) << 32) | (u64)node;
                atomicMin(&keyA[row], key);
            }
        }
    }
    __syncthreads();
    if (t < TM) {
        int b = (int)(keyA[t] & 0xffffffffu);
        bmuS[t] = b;
        out[BMUOFF + R0 + t] = (float)b;
    }
    __syncthreads();

    // ---- copy table ----
    for (int v = t; v < TM * 6; v += NT) {
        int row2 = v / 6, s = v - row2 * 6;
        int b = bmuS[row2];
        int idx;
        if (s <= 1) {
            idx = b;
        } else {
            int k1 = b >> 4, k2 = b & 15;
            if      (s == 2) idx = (((k1 + 15) & 15) << 4) + k2;   // up
            else if (s == 3) idx = (((k1 + 1)  & 15) << 4) + k2;   // down
            else if (s == 4) idx = (k1 << 4) + ((k2 + 1)  & 15);   // right
            else             idx = (k1 << 4) + ((k2 + 15) & 15);   // left
        }
        u64 dstoff = (s == 0)
            ? (u64)(R0 + row2) * LATENT
            : (u64)NBOFF + ((u64)(R0 + row2) * 5 + (s - 1)) * LATENT;
        tab[v] = (dstoff << 8) | (u64)(u32)idx;
    }
    __syncthreads();

    // ---- flat coalesced copies, MLP-8 batches: 768 copies x 64 float4 ----
    #pragma unroll
    for (int bb = 0; bb < 12; bb++) {
        float4 vv[8]; u64 doff[8];
        #pragma unroll
        for (int i = 0; i < 8; i++) {
            int v = (bb * 8 + i) * NT + t;
            u64 pk = tab[v >> 6];
            int idx = (int)(pk & 0xff);
            int seg = v & 63;
            doff[i] = (pk >> 8) + (u64)(seg * 4);
            vv[i] = ((const float4*)(E + (size_t)idx * LATENT))[seg];
        }
        #pragma unroll
        for (int i = 0; i < 8; i++)
            *(float4*)(out + doff[i]) = vv[i];
    }
}

extern "C" void kernel_launch(void* const* d_in, const int* in_sizes, int n_in,
                              void* d_out, int out_size) {
    const float* Z = (const float*)d_in[0];
    const float* E = (const float*)d_in[1];
    const int*   A = (const int*)d_in[2];
    float* out = (float*)d_out;

    cudaFuncSetAttribute(som_main, cudaFuncAttributeMaxDynamicSharedMemorySize, SMEM_BYTES);
    som_main<<<GRID, NT, SMEM_BYTES>>>(Z, E, A, out);
}

// round 17
// speedup vs baseline: 1.1590x; 1.1590x over previous
#include <cuda_runtime.h>
#include <cuda_fp16.h>
#include <cstdint>
#include <cstddef>

typedef unsigned long long u64;
typedef unsigned int u32;

#define NROWS  65536
#define LATENT 256
#define NNODES 256
#define TM     128
#define NT     512
#define GRID   (NROWS / TM)   // 512
#define EPSF   1.1920929e-7f
#define MARGIN 0.02f
#define CAP    2048

// ---- smem layout (byte offsets from 1KB-aligned base) ----
#define BSM(c)  ((c) * 32768)              // 4 x 32KB persistent fp16 B chunks (cp.async once)
#define AST(s)  (131072 + (s) * 16384)     // 2 x 16KB fp16 A stages
#define T_LIST  131072                     // overlays A stages (dead post-GEMM)
#define T_E2RAW 163840
#define T_E2D   164864
#define T_Z2P   165888
#define T_Z2RAW 167936
#define T_Z2PP  168448
#define T_RQM   168960
#define T_RQS   171008
#define T_QTHR  173056
#define T_RQSI  173568
#define T_KEY   174080
#define T_BMU   175104
#define T_CNT   175616
#define T_TAB   175632                     // 768 * 8 = 6144
#define SMEM_BYTES (181776 + 1024)

__device__ __align__(1024) unsigned char g_Bt[4][256 * 64 * 2];   // prebuilt fp16 E tiles (128KB)
__device__ float g_e2[NNODES];

__device__ __forceinline__ u32 smaddr(const void* p) { return (u32)__cvta_generic_to_shared(p); }
__device__ __forceinline__ u32 toff(int row, int kbyte) {
    u32 o = (u32)(row * 128 + kbyte);
    return o ^ ((o >> 3) & 0x70);          // SW128 (XORs bits 4-6; 8/16B-aligned stores stay aligned)
}
__device__ __forceinline__ void cp16(u32 dst, const void* src) {
    asm volatile("cp.async.cg.shared.global [%0], [%1], 16;" :: "r"(dst), "l"(src));
}
__device__ __forceinline__ void cp_commit() { asm volatile("cp.async.commit_group;" ::: "memory"); }
__device__ __forceinline__ void cp_wait0()  { asm volatile("cp.async.wait_group 0;" ::: "memory"); }
__device__ __forceinline__ void ldsm4(u32* r, u32 addr) {
    asm volatile("ldmatrix.sync.aligned.m8n8.x4.shared.b16 {%0,%1,%2,%3}, [%4];"
                 : "=r"(r[0]), "=r"(r[1]), "=r"(r[2]), "=r"(r[3]) : "r"(addr));
}
__device__ __forceinline__ void mma16816(float* d, const u32* a, u32 b0, u32 b1) {
    asm volatile("mma.sync.aligned.m16n8k16.row.col.f32.f16.f16.f32 "
                 "{%0,%1,%2,%3}, {%4,%5,%6,%7}, {%8,%9}, {%0,%1,%2,%3};"
                 : "+f"(d[0]), "+f"(d[1]), "+f"(d[2]), "+f"(d[3])
                 : "r"(a[0]), "r"(a[1]), "r"(a[2]), "r"(a[3]), "r"(b0), "r"(b1));
}
__device__ __forceinline__ u64 packf2(float lo, float hi) {
    u64 d; asm("mov.b64 %0, {%1, %2};" : "=l"(d) : "f"(lo), "f"(hi)); return d;
}
__device__ __forceinline__ void unpackf2(float& lo, float& hi, u64 v) {
    asm("mov.b64 {%0, %1}, %2;" : "=f"(lo), "=f"(hi) : "l"(v));
}
__device__ __forceinline__ u64 add2(u64 a, u64 b) {
    u64 d; asm("add.rn.f32x2 %0, %1, %2;" : "=l"(d) : "l"(a), "l"(b)); return d;
}
__device__ __forceinline__ u64 mul2(u64 a, u64 b) {
    u64 d; asm("mul.rn.f32x2 %0, %1, %2;" : "=l"(d) : "l"(a), "l"(b)); return d;
}
__device__ __forceinline__ u64 fma2(u64 a, u64 b, u64 c) {
    u64 d; asm("fma.rn.f32x2 %0, %1, %2, %3;" : "=l"(d) : "l"(a), "l"(b), "l"(c)); return d;
}
__device__ __forceinline__ u64 cvt4fp16(float4 v) {
    __half2 p0 = __floats2half2_rn(v.x, v.y);
    __half2 p1 = __floats2half2_rn(v.z, v.w);
    u32 a = *(u32*)&p0, b = *(u32*)&p1;
    return ((u64)b << 32) | (u64)a;
}

// ---------- prep (minimal): fp16 B tiles + e2 ----------
__global__ void __launch_bounds__(256, 1)
prep_kernel(const float* __restrict__ E) {
    int tid = blockIdx.x * 256 + threadIdx.x;   // 64 x 256 = 16384
    if (tid < 8192) {   // 4 chunks x 256 nodes x 8 kgroups
        int chunk = tid >> 11, node = (tid >> 3) & 255, kg = tid & 7;
        const float* src = E + (size_t)node * LATENT + chunk * 64 + kg * 8;
        float4 w0 = *(const float4*)(src);
        float4 w1 = *(const float4*)(src + 4);
        ulonglong2 pk;
        pk.x = cvt4fp16(w0);
        pk.y = cvt4fp16(w1);
        *(ulonglong2*)(g_Bt[chunk] + toff(node, kg * 16)) = pk;
    } else if (tid < 8192 + NNODES) {
        int node = tid - 8192;
        const float4* er = (const float4*)(E + (size_t)node * LATENT);
        float s = 0.f;
        #pragma unroll 8
        for (int i = 0; i < 64; i++) { float4 v = er[i]; s += v.x*v.x + v.y*v.y + v.z*v.z + v.w*v.w; }
        g_e2[node] = s;
    }
}

// ---------- main ----------
__global__ void __launch_bounds__(NT, 1)
som_main(const float* __restrict__ Z, const float* __restrict__ E,
         const int* __restrict__ Alpha, float* __restrict__ out)
{
    extern __shared__ char smraw[];
    char* SB = (char*)(((uintptr_t)smraw + 1023) & ~(uintptr_t)1023);
    float* e2raw = (float*)(SB + T_E2RAW);
    float* e2d   = (float*)(SB + T_E2D);
    float* z2p   = (float*)(SB + T_Z2P);
    float* z2raw = (float*)(SB + T_Z2RAW);
    float* z2pp  = (float*)(SB + T_Z2PP);
    float* rqm   = (float*)(SB + T_RQM);
    float* rqsum = (float*)(SB + T_RQS);
    float* qthr  = (float*)(SB + T_QTHR);
    float* rqs   = (float*)(SB + T_RQSI);
    u64*   keyA  = (u64*)(SB + T_KEY);
    int*   bmuS  = (int*)(SB + T_BMU);
    int*   cnt   = (int*)(SB + T_CNT);
    u64*   tab   = (u64*)(SB + T_TAB);
    u32*   list  = (u32*)(SB + T_LIST);

    const int t = threadIdx.x, wid = t >> 5, lane = t & 31;
    const int g = lane >> 2, qd = lane & 3;
    const int R0 = blockIdx.x * TM;
    const int wr = (wid >> 2) * 32, wc = (wid & 3) * 64;
    const int arow = t >> 2, akp = t & 3;   // A build: 4 threads/row, 16 floats each

    // alpha (robust)
    int ai = Alpha[0];
    float aa = (ai > 0 && ai < 1000000) ? (float)ai : __int_as_float(ai);
    const float inva = 1.0f / aa;
    const float coef = -(aa + 1.0f) * 0.5f;
    const bool fast = (aa == 10.0f);
    const u64 cm2 = packf2(-2.f * inva, -2.f * inva);

    // ---- prologue: cp.async the ENTIRE B (128KB, all 4 chunks) once ----
    {
        const unsigned char* bsrc = (const unsigned char*)g_Bt;
        #pragma unroll
        for (int i = 0; i < 16; i++) {
            int o = (t + NT * i) * 16;      // covers [0, 131072)
            cp16(smaddr(SB + o), bsrc + o);
        }
        cp_commit();
    }

    if (t < TM) keyA[t] = ~0ull;
    if (t == 0) *cnt = 0;

    float z2acc = 0.f;

    // A chunk 0: issue DRAM loads, then tail loads, then convert+store
    float4 a0[4];
    {
        const float4* zsrc = (const float4*)(Z + (size_t)(R0 + arow) * LATENT + akp * 16);
        a0[0] = zsrc[0]; a0[1] = zsrc[1]; a0[2] = zsrc[2]; a0[3] = zsrc[3];
    }
    if (t < NNODES) {
        float e = g_e2[t];
        e2raw[t] = e;
        e2d[t]   = e * inva;
    }
    {
        #pragma unroll
        for (int i = 0; i < 4; i++) {
            float4 w = a0[i];
            z2acc = fmaf(w.x,w.x,fmaf(w.y,w.y,fmaf(w.z,w.z,fmaf(w.w,w.w,z2acc))));
        }
        ulonglong2 pk0, pk1;
        pk0.x = cvt4fp16(a0[0]); pk0.y = cvt4fp16(a0[1]);
        pk1.x = cvt4fp16(a0[2]); pk1.y = cvt4fp16(a0[3]);
        *(ulonglong2*)(SB + AST(0) + toff(arow, akp * 32))      = pk0;
        *(ulonglong2*)(SB + AST(0) + toff(arow, akp * 32 + 16)) = pk1;
    }
    cp_wait0();   // own B copies done; barrier at loop top publishes all

    // ---- GEMM: 4 chunks; B persistent, A double-buffered in-loop ----
    float acc[2][8][4];
    #pragma unroll
    for (int mt = 0; mt < 2; mt++)
        #pragma unroll
        for (int j = 0; j < 8; j++)
            #pragma unroll
            for (int c4 = 0; c4 < 4; c4++) acc[mt][j][c4] = 0.f;

    const int la = lane & 15, kh = lane >> 4;
    for (int c = 0; c < 4; c++) {
        const int s = c & 1;
        __syncthreads();   // A stage s built by all (+ B visible on c==0); MMAs done with s^1

        if (c < 3) {       // build A chunk c+1 into stage s^1 (proven free under MMA slack)
            const float4* zsrc = (const float4*)(Z + (size_t)(R0 + arow) * LATENT + (c + 1) * 64 + akp * 16);
            float4 w0 = zsrc[0], w1 = zsrc[1], w2 = zsrc[2], w3 = zsrc[3];
            z2acc = fmaf(w0.x,w0.x,fmaf(w0.y,w0.y,fmaf(w0.z,w0.z,fmaf(w0.w,w0.w,z2acc))));
            z2acc = fmaf(w1.x,w1.x,fmaf(w1.y,w1.y,fmaf(w1.z,w1.z,fmaf(w1.w,w1.w,z2acc))));
            z2acc = fmaf(w2.x,w2.x,fmaf(w2.y,w2.y,fmaf(w2.z,w2.z,fmaf(w2.w,w2.w,z2acc))));
            z2acc = fmaf(w3.x,w3.x,fmaf(w3.y,w3.y,fmaf(w3.z,w3.z,fmaf(w3.w,w3.w,z2acc))));
            ulonglong2 pk0, pk1;
            pk0.x = cvt4fp16(w0); pk0.y = cvt4fp16(w1);
            pk1.x = cvt4fp16(w2); pk1.y = cvt4fp16(w3);
            *(ulonglong2*)(SB + AST(1 - s) + toff(arow, akp * 32))      = pk0;
            *(ulonglong2*)(SB + AST(1 - s) + toff(arow, akp * 32 + 16)) = pk1;
        }

        const u32 sAa = smaddr(SB + AST(s));
        const u32 sBa = smaddr(SB + BSM(c));
        #pragma unroll
        for (int ks = 0; ks < 4; ks++) {
            const int kb = ks * 32 + kh * 16;
            u32 af[2][4];
            ldsm4(af[0], sAa + toff(wr + la, kb));
            ldsm4(af[1], sAa + toff(wr + 16 + la, kb));
            u32 bf[4][4];
            #pragma unroll
            for (int p = 0; p < 4; p++)
                ldsm4(bf[p], sBa + toff(wc + p * 16 + la, kb));
            #pragma unroll
            for (int mt = 0; mt < 2; mt++)
                #pragma unroll
                for (int j = 0; j < 8; j++)
                    mma16816(acc[mt][j], af[mt], bf[j >> 1][j & 1], bf[j >> 1][(j & 1) + 2]);
        }
    }

    // ---- z2 finalize ----
    z2p[arow * 4 + akp] = z2acc;
    __syncthreads();
    if (t < TM) {
        float z = z2p[4*t] + z2p[4*t+1] + z2p[4*t+2] + z2p[4*t+3];
        z2raw[t] = z;
        z2pp[t]  = fmaf(z, inva, 1.0f);
    }
    __syncthreads();

    // ---- q eval (rsqrt(p^11) fast path), per-row qmax + qsum ----
    u64 ed2[8];
    #pragma unroll
    for (int j = 0; j < 8; j++) ed2[j] = *(const u64*)(e2d + wc + j * 8 + 2 * qd);
    float qmaxr[4], qsumr[4];
    #pragma unroll
    for (int mt = 0; mt < 2; mt++) {
        #pragma unroll
        for (int hf = 0; hf < 2; hf++) {
            const int row = wr + mt * 16 + hf * 8 + g;
            const u64 zp = packf2(z2pp[row], z2pp[row]);
            u64 qs2 = 0ull;
            float qmax = 0.f;
            #pragma unroll
            for (int j = 0; j < 8; j++) {
                u64 a2 = packf2(acc[mt][j][2*hf], acc[mt][j][2*hf+1]);
                u64 p  = fma2(a2, cm2, add2(zp, ed2[j]));   // p = 1 + d/alpha
                float q0, q1;
                if (fast) {
                    u64 x2 = mul2(p, p);
                    u64 x4 = mul2(x2, x2);
                    u64 x8 = mul2(x4, x4);
                    u64 x11 = mul2(mul2(x8, x2), p);
                    float lo, hi; unpackf2(lo, hi, x11);
                    q0 = rsqrtf(lo); q1 = rsqrtf(hi);
                } else {
                    float lo, hi; unpackf2(lo, hi, p);
                    q0 = exp2f(coef * __log2f(lo));
                    q1 = exp2f(coef * __log2f(hi));
                }
                qs2 = add2(qs2, packf2(q0, q1));
                qmax = fmaxf(qmax, fmaxf(q0, q1));
                acc[mt][j][2*hf] = q0;
                acc[mt][j][2*hf+1] = q1;
            }
            float slo, shi; unpackf2(slo, shi, qs2);
            qmaxr[mt*2+hf] = qmax;
            qsumr[mt*2+hf] = slo + shi;
        }
    }
    #pragma unroll
    for (int i = 0; i < 4; i++) {
        qmaxr[i] = fmaxf(qmaxr[i], __shfl_xor_sync(0xffffffffu, qmaxr[i], 1));
        qmaxr[i] = fmaxf(qmaxr[i], __shfl_xor_sync(0xffffffffu, qmaxr[i], 2));
        qsumr[i] += __shfl_xor_sync(0xffffffffu, qsumr[i], 1);
        qsumr[i] += __shfl_xor_sync(0xffffffffu, qsumr[i], 2);
    }
    if (qd == 0) {
        #pragma unroll
        for (int i = 0; i < 4; i++) {
            const int row = wr + (i >> 1) * 16 + (i & 1) * 8 + g;
            rqm[row * 4 + (wid & 3)]   = qmaxr[i];
            rqsum[row * 4 + (wid & 3)] = qsumr[i];
        }
    }
    __syncthreads();
    if (t < TM) {
        float qm = 0.f, s = 0.f;
        #pragma unroll
        for (int k = 0; k < 4; k++) { qm = fmaxf(qm, rqm[t*4+k]); s += rqsum[t*4+k]; }
        rqs[t] = 1.0f / s;
        float pmin = exp2f(__log2f(qm) / coef);
        float y = pmin + MARGIN * inva;
        float qt;
        if (fast) {
            float y2 = y*y, y4 = y2*y2, y8 = y4*y4;
            qt = rsqrtf(y8 * y2 * y);
        } else {
            qt = exp2f(coef * __log2f(y));
        }
        qthr[t] = qt;
    }
    __syncthreads();

    const size_t NBOFF  = (size_t)NROWS * 256;
    const size_t QOFF   = (size_t)NROWS * 1536;
    const size_t BMUOFF = (size_t)NROWS * 1792;

    // ---- q stores first (early DRAM burst) ----
    #pragma unroll
    for (int mt = 0; mt < 2; mt++)
        #pragma unroll
        for (int hf = 0; hf < 2; hf++) {
            const int row = wr + mt * 16 + hf * 8 + g;
            const float rq = rqs[row];
            #pragma unroll
            for (int j = 0; j < 8; j++) {
                float2 qv;
                qv.x = fmaf(acc[mt][j][2*hf],   rq, EPSF);
                qv.y = fmaf(acc[mt][j][2*hf+1], rq, EPSF);
                *(float2*)(out + QOFF + (size_t)(R0 + row) * NNODES + wc + j * 8 + 2 * qd) = qv;
            }
        }

    // ---- candidate collection (list overlays dead A stages) ----
    #pragma unroll
    for (int mt = 0; mt < 2; mt++)
        #pragma unroll
        for (int hf = 0; hf < 2; hf++) {
            const int row = wr + mt * 16 + hf * 8 + g;
            const float th = qthr[row];
            #pragma unroll
            for (int j = 0; j < 8; j++)
                #pragma unroll
                for (int u2 = 0; u2 < 2; u2++) {
                    if (acc[mt][j][2*hf+u2] >= th) {
                        int idx = atomicAdd(cnt, 1);
                        if (idx < CAP)
                            list[idx] = ((u32)row << 8) | (u32)(wc + j * 8 + 2 * qd + u2);
                    }
                }
        }
    __syncthreads();

    // ---- exact fp32 refinement: one warp per candidate ----
    {
        const int n = min(*cnt, CAP);
        for (int e = wid; e < n; e += 16) {
            u32 ent = list[e];
            int row = ent >> 8, node = ent & 255;
            const float4* zr = (const float4*)(Z + (size_t)(R0 + row) * LATENT);
            const float4* er = (const float4*)(E + (size_t)node * LATENT);
            float4 za = zr[lane*2], zb = zr[lane*2+1];
            float4 ea = er[lane*2], eb = er[lane*2+1];
            float d = za.x*ea.x + za.y*ea.y + za.z*ea.z + za.w*ea.w
                    + zb.x*eb.x + zb.y*eb.y + zb.z*eb.z + zb.w*eb.w;
            #pragma unroll
            for (int o = 16; o > 0; o >>= 1) d += __shfl_down_sync(0xffffffffu, d, o);
            if (lane == 0) {
                float dex = fmaxf(z2raw[row] + e2raw[node] - 2.f * d, 0.f);
                u64 key = ((u64)__float_as_uint(dex) << 32) | (u64)node;
                atomicMin(&keyA[row], key);
            }
        }
    }
    __syncthreads();
    if (t < TM) {
        int b = (int)(keyA[t] & 0xffffffffu);
        bmuS[t] = b;
        out[BMUOFF + R0 + t] = (float)b;
    }
    __syncthreads();

    // ---- copy table ----
    for (int v = t; v < TM * 6; v += NT) {
        int row2 = v / 6, s = v - row2 * 6;
        int b = bmuS[row2];
        int idx;
        if (s <= 1) {
            idx = b;
        } else {
            int k1 = b >> 4, k2 = b & 15;
            if      (s == 2) idx = (((k1 + 15) & 15) << 4) + k2;   // up
            else if (s == 3) idx = (((k1 + 1)  & 15) << 4) + k2;   // down
            else if (s == 4) idx = (k1 << 4) + ((k2 + 1)  & 15);   // right
            else             idx = (k1 << 4) + ((k2 + 15) & 15);   // left
        }
        u64 dstoff = (s == 0)
            ? (u64)(R0 + row2) * LATENT
            : (u64)NBOFF + ((u64)(R0 + row2) * 5 + (s - 1)) * LATENT;
        tab[v] = (dstoff << 8) | (u64)(u32)idx;
    }
    __syncthreads();

    // ---- flat coalesced copies, MLP-8 batches: 768 copies x 64 float4 ----
    #pragma unroll
    for (int bb = 0; bb < 12; bb++) {
        float4 vv[8]; u64 doff[8];
        #pragma unroll
        for (int i = 0; i < 8; i++) {
            int v = (bb * 8 + i) * NT + t;
            u64 pk = tab[v >> 6];
            int idx = (int)(pk & 0xff);
            int seg = v & 63;
            doff[i] = (pk >> 8) + (u64)(seg * 4);
            vv[i] = ((const float4*)(E + (size_t)idx * LATENT))[seg];
        }
        #pragma unroll
        for (int i = 0; i < 8; i++)
            *(float4*)(out + doff[i]) = vv[i];
    }
}

extern "C" void kernel_launch(void* const* d_in, const int* in_sizes, int n_in,
                              void* d_out, int out_size) {
    const float* Z = (const float*)d_in[0];
    const float* E = (const float*)d_in[1];
    const int*   A = (const int*)d_in[2];
    float* out = (float*)d_out;

    prep_kernel<<<64, 256>>>(E);
    cudaFuncSetAttribute(som_main, cudaFuncAttributeMaxDynamicSharedMemorySize, SMEM_BYTES);
    som_main<<<GRID, NT, SMEM_BYTES>>>(Z, E, A, out);
}